// round 13
// baseline (speedup 1.0000x reference)
#include <cuda_runtime.h>
#include <math.h>

// ---------------- problem constants ----------------
#define Hh 256
#define Bsz 128
#define Asz 24
#define Nn (Bsz*Asz)          // 3072 nodes
#define Ee (Bsz*Asz*Asz)      // 73728 edges
#define MAXA 103
#define TIMED 256
#define TEXTD 128
#define NFREQ 10
#define NLAYERS 4
#define DISD (NFREQ*2*3)      // 60
#define EDGE_IN (2*Hh+9+DISD) // 581
#define LD_PAD 72             // 9 lat + 60 demb, padded to 72

// output layout: atom_types_out | lattice_out | coords_out | nf
#define O_TYPES 0
#define O_LATT  (Nn*MAXA)
#define O_COORD (O_LATT + Bsz*9)
#define O_NF    (O_COORD + Nn*3)

typedef unsigned long long ull;

// ---------------- scratch ----------------
__device__ float g_nf[Nn*Hh];
__device__ float g_PQ[Nn*2*Hh];
__device__ float g_no1[Nn*Hh];
__device__ float g_agg[Nn*Hh];
__device__ float g_ef1[(size_t)Ee*Hh];
__device__ float g_latdemb[(size_t)Ee*LD_PAD];
__device__ float g_w1r[Hh*LD_PAD];
__device__ float g_cond[Bsz*2*Hh];
__device__ float g_latips[Bsz*9];
__device__ float g_gfeat[Bsz*Hh];
__device__ float g_lattmp[Bsz*9];

// tanh-based silu: 1 MUFU instead of 2 (EX2+RCP). abs err ~1e-4 -> rel_err ~3e-6 net (validated R7-9).
__device__ __forceinline__ float siluf(float x){
    float h = 0.5f*x, t;
    asm("tanh.approx.f32 %0, %1;" : "=f"(t) : "f"(h));
    return h*(1.f+t);
}
__device__ __forceinline__ ull pack2(float x, float y){
    ull r; asm("mov.b64 %0, {%1, %2};" : "=l"(r) : "f"(x), "f"(y)); return r;
}
__device__ __forceinline__ void unpack2(ull v, float &x, float &y){
    asm("mov.b64 {%0, %1}, %2;" : "=f"(x), "=f"(y) : "l"(v));
}
__device__ __forceinline__ void fma2(ull &d, ull a, ull b){
    asm("fma.rn.f32x2 %0, %1, %2, %0;" : "+l"(d) : "l"(a), "l"(b));
}

// ================= fast node GEMM: 64x64x8, TM=TN=4, f32x2 =================
// B smem: [BK][16 groups][6] pad (conflict-free). A read as 1x LDS.128.
template<bool CONCAT,bool WSPLIT,bool ACT,bool RESID>
__global__ __launch_bounds__(256) void node_gemm(
    const float* __restrict__ A,
    const float* __restrict__ A2, float s2,
    const float* __restrict__ W, int ldw,
    const float* __restrict__ bias,
    const float* resid,
    float* C, int Nout, int K)
{
    const int BM=64,BN=64,BK=8,TM=4,TN=4,NT=256;
    __shared__ __align__(16) float As[2][BK][BM];
    __shared__ __align__(16) float Bs2[2][BK][16][6];
    const int tid=threadIdx.x;
    const int tc=tid%(BN/TN), tr=tid/(BN/TN);
    const int m0=blockIdx.y*BM, n0=blockIdx.x*BN;

    ull acc[TM][TN/2];
    #pragma unroll
    for(int i=0;i<TM;i++)
        #pragma unroll
        for(int j=0;j<TN/2;j++) acc[i][j]=0ULL;

    float ra[2], rb[2];
    #pragma unroll
    for(int u=0;u<2;u++){
        int i=tid+u*NT; int mm=i/BK, kk=i%BK;
        int gm=m0+mm, gk=kk;
        if(CONCAT) ra[u] = (gk<Hh)? A[(size_t)gm*Hh+gk] : A2[(size_t)gm*Hh+gk-Hh]*s2;
        else       ra[u] = A[(size_t)gm*K+gk];
    }
    #pragma unroll
    for(int u=0;u<2;u++){
        int i=tid+u*NT; int nn=i/BK, kk=i%BK;
        int gn=n0+nn, gk=kk;
        if(WSPLIT) rb[u] = (gn<Hh)? W[(size_t)gn*ldw+gk] : W[(size_t)(gn-Hh)*ldw+Hh+gk];
        else       rb[u] = W[(size_t)gn*ldw+gk];
    }
    #pragma unroll
    for(int u=0;u<2;u++){int i=tid+u*NT; As[0][i%BK][i/BK]=ra[u];}
    #pragma unroll
    for(int u=0;u<2;u++){int i=tid+u*NT; int nn=i/BK; Bs2[0][i%BK][nn>>2][nn&3]=rb[u];}
    __syncthreads();

    const int ntile=K/BK;
    for(int t=0;t<ntile;t++){
        int cur=t&1;
        if(t+1<ntile){
            int k0=(t+1)*BK;
            #pragma unroll
            for(int u=0;u<2;u++){
                int i=tid+u*NT; int mm=i/BK, kk=i%BK;
                int gm=m0+mm, gk=k0+kk;
                if(CONCAT) ra[u] = (gk<Hh)? A[(size_t)gm*Hh+gk] : A2[(size_t)gm*Hh+gk-Hh]*s2;
                else       ra[u] = A[(size_t)gm*K+gk];
            }
            #pragma unroll
            for(int u=0;u<2;u++){
                int i=tid+u*NT; int nn=i/BK, kk=i%BK;
                int gn=n0+nn, gk=k0+kk;
                if(WSPLIT) rb[u] = (gn<Hh)? W[(size_t)gn*ldw+gk] : W[(size_t)(gn-Hh)*ldw+Hh+gk];
                else       rb[u] = W[(size_t)gn*ldw+gk];
            }
        }
        #pragma unroll
        for(int kk=0;kk<BK;kk++){
            ull av[TM], bv[TN/2];
            float4 a0=*(const float4*)&As[cur][kk][tr*TM];
            av[0]=pack2(a0.x,a0.x); av[1]=pack2(a0.y,a0.y);
            av[2]=pack2(a0.z,a0.z); av[3]=pack2(a0.w,a0.w);
            #pragma unroll
            for(int j=0;j<TN/2;j++) bv[j]=*reinterpret_cast<const ull*>(&Bs2[cur][kk][tc][2*j]);
            #pragma unroll
            for(int i=0;i<TM;i++)
                #pragma unroll
                for(int j=0;j<TN/2;j++) fma2(acc[i][j],av[i],bv[j]);
        }
        if(t+1<ntile){
            int nb=cur^1;
            #pragma unroll
            for(int u=0;u<2;u++){int i=tid+u*NT; As[nb][i%BK][i/BK]=ra[u];}
            #pragma unroll
            for(int u=0;u<2;u++){int i=tid+u*NT; int nn=i/BK; Bs2[nb][i%BK][nn>>2][nn&3]=rb[u];}
            __syncthreads();
        }
    }

    #pragma unroll
    for(int i=0;i<TM;i++){
        int gm=m0+tr*TM+i;
        #pragma unroll
        for(int j=0;j<TN/2;j++){
            float v0,v1; unpack2(acc[i][j],v0,v1);
            int col=n0+tc*TN+2*j;
            if(bias){ v0+=bias[col]; v1+=bias[col+1]; }
            if(ACT){ v0=siluf(v0); v1=siluf(v1); }
            if(RESID){ v0+=resid[(size_t)gm*Nout+col]; v1+=resid[(size_t)gm*Nout+col+1]; }
            C[(size_t)gm*Nout+col]=v0; C[(size_t)gm*Nout+col+1]=v1;
        }
    }
}

// ================= edge GEMM1: ef1 = silu(latdemb@W1r^T + P[e0]+Q[e1]+b1) ====
// 128x128x8, TM=TN=8, K=72. B: [BK][16][10] pad; A read as 2x LDS.128.
__global__ __launch_bounds__(256) void edge1_gemm(
    const float* __restrict__ A,    // [Ee][72]
    const float* __restrict__ W,    // [256][72] packed
    const float* __restrict__ bias, // [256]
    const float* __restrict__ PQ,   // [Nn][512]
    float* __restrict__ C)          // [Ee][256]
{
    const int BM=128,BN=128,BK=8,TM=8,TN=8,NT=256,K=LD_PAD;
    __shared__ __align__(16) float As[2][BK][BM];
    __shared__ __align__(16) float Bs2[2][BK][16][10];
    const int tid=threadIdx.x;
    const int tc=tid%(BN/TN), tr=tid/(BN/TN);
    const int m0=blockIdx.y*BM, n0=blockIdx.x*BN;

    ull acc[TM][TN/2];
    #pragma unroll
    for(int i=0;i<TM;i++)
        #pragma unroll
        for(int j=0;j<TN/2;j++) acc[i][j]=0ULL;

    float ra[4], rb[4];
    #pragma unroll
    for(int u=0;u<4;u++){int i=tid+u*NT; ra[u]=A[(size_t)(m0+i/BK)*K + i%BK];}
    #pragma unroll
    for(int u=0;u<4;u++){int i=tid+u*NT; rb[u]=W[(size_t)(n0+i/BK)*K + i%BK];}
    #pragma unroll
    for(int u=0;u<4;u++){int i=tid+u*NT; As[0][i%BK][i/BK]=ra[u];}
    #pragma unroll
    for(int u=0;u<4;u++){int i=tid+u*NT; int nn=i/BK; Bs2[0][i%BK][nn>>3][nn&7]=rb[u];}
    __syncthreads();

    const int ntile=K/BK; // 9
    for(int t=0;t<ntile;t++){
        int cur=t&1;
        if(t+1<ntile){
            int k0=(t+1)*BK;
            #pragma unroll
            for(int u=0;u<4;u++){int i=tid+u*NT; ra[u]=A[(size_t)(m0+i/BK)*K + k0 + i%BK];}
            #pragma unroll
            for(int u=0;u<4;u++){int i=tid+u*NT; rb[u]=W[(size_t)(n0+i/BK)*K + k0 + i%BK];}
        }
        #pragma unroll
        for(int kk=0;kk<BK;kk++){
            ull av[TM], bv[TN/2];
            const float4* ar=(const float4*)&As[cur][kk][tr*TM];
            float4 a0=ar[0], a1=ar[1];
            av[0]=pack2(a0.x,a0.x); av[1]=pack2(a0.y,a0.y);
            av[2]=pack2(a0.z,a0.z); av[3]=pack2(a0.w,a0.w);
            av[4]=pack2(a1.x,a1.x); av[5]=pack2(a1.y,a1.y);
            av[6]=pack2(a1.z,a1.z); av[7]=pack2(a1.w,a1.w);
            #pragma unroll
            for(int j=0;j<TN/2;j++) bv[j]=*reinterpret_cast<const ull*>(&Bs2[cur][kk][tc][2*j]);
            #pragma unroll
            for(int i=0;i<TM;i++)
                #pragma unroll
                for(int j=0;j<TN/2;j++) fma2(acc[i][j],av[i],bv[j]);
        }
        if(t+1<ntile){
            int nb=cur^1;
            #pragma unroll
            for(int u=0;u<4;u++){int i=tid+u*NT; As[nb][i%BK][i/BK]=ra[u];}
            #pragma unroll
            for(int u=0;u<4;u++){int i=tid+u*NT; int nn=i/BK; Bs2[nb][i%BK][nn>>3][nn&7]=rb[u];}
            __syncthreads();
        }
    }

    const int col0 = n0 + tc*TN;
    const float4 b4a = *(const float4*)(bias+col0);
    const float4 b4b = *(const float4*)(bias+col0+4);
    #pragma unroll
    for(int i=0;i<TM;i++){
        int gm=m0+tr*TM+i;
        int b  = gm/(Asz*Asz), w = gm%(Asz*Asz);
        int e0 = b*Asz + w/Asz, e1 = b*Asz + w%Asz;
        const float4* pp=(const float4*)(PQ + (size_t)e0*(2*Hh) + col0);
        const float4* qq=(const float4*)(PQ + (size_t)e1*(2*Hh) + Hh + col0);
        float4 pa=pp[0], pb=pp[1], qa=qq[0], qb=qq[1];
        float v[8];
        #pragma unroll
        for(int j=0;j<TN/2;j++) unpack2(acc[i][j], v[2*j], v[2*j+1]);
        v[0]=siluf(v[0]+b4a.x+pa.x+qa.x); v[1]=siluf(v[1]+b4a.y+pa.y+qa.y);
        v[2]=siluf(v[2]+b4a.z+pa.z+qa.z); v[3]=siluf(v[3]+b4a.w+pa.w+qa.w);
        v[4]=siluf(v[4]+b4b.x+pb.x+qb.x); v[5]=siluf(v[5]+b4b.y+pb.y+qb.y);
        v[6]=siluf(v[6]+b4b.z+pb.z+qb.z); v[7]=siluf(v[7]+b4b.w+pb.w+qb.w);
        float4* o=(float4*)(C + (size_t)gm*Hh + col0);
        o[0]=make_float4(v[0],v[1],v[2],v[3]);
        o[1]=make_float4(v[4],v[5],v[6],v[7]);
    }
}

// ===== edge GEMM2 + fused segment-mean: agg[n] = mean_{24 edges} silu(ef1@W2^T+b2)
// 96x128x8, TM=6, TN=8. B padded [BK][16][10]; A read as 3x LDS.64. No atomics.
__global__ __launch_bounds__(256) void edge2_gemm(
    const float* __restrict__ A,    // ef1 [Ee][256]
    const float* __restrict__ W,    // ew2 [256][256]
    const float* __restrict__ bias, // [256]
    float* __restrict__ agg)        // [Nn][256]
{
    const int BM=96,BN=128,BK=8,TM=6,TN=8,NT=256,K=Hh;
    __shared__ __align__(16) float As[2][BK][BM];
    __shared__ __align__(16) float Bs2[2][BK][16][10];
    __shared__ float red[16][BN];
    const int tid=threadIdx.x;
    const int tc=tid%(BN/TN), tr=tid/(BN/TN);
    const int m0=blockIdx.y*BM, n0=blockIdx.x*BN;

    ull acc[TM][TN/2];
    #pragma unroll
    for(int i=0;i<TM;i++)
        #pragma unroll
        for(int j=0;j<TN/2;j++) acc[i][j]=0ULL;

    float ra[3], rb[4];
    #pragma unroll
    for(int u=0;u<3;u++){int i=tid+u*NT; ra[u]=A[(size_t)(m0+i/BK)*K + i%BK];}
    #pragma unroll
    for(int u=0;u<4;u++){int i=tid+u*NT; rb[u]=W[(size_t)(n0+i/BK)*K + i%BK];}
    #pragma unroll
    for(int u=0;u<3;u++){int i=tid+u*NT; As[0][i%BK][i/BK]=ra[u];}
    #pragma unroll
    for(int u=0;u<4;u++){int i=tid+u*NT; int nn=i/BK; Bs2[0][i%BK][nn>>3][nn&7]=rb[u];}
    __syncthreads();

    const int ntile=K/BK; // 32
    for(int t=0;t<ntile;t++){
        int cur=t&1;
        if(t+1<ntile){
            int k0=(t+1)*BK;
            #pragma unroll
            for(int u=0;u<3;u++){int i=tid+u*NT; ra[u]=A[(size_t)(m0+i/BK)*K + k0 + i%BK];}
            #pragma unroll
            for(int u=0;u<4;u++){int i=tid+u*NT; rb[u]=W[(size_t)(n0+i/BK)*K + k0 + i%BK];}
        }
        #pragma unroll
        for(int kk=0;kk<BK;kk++){
            ull av[TM], bv[TN/2];
            const float2* ar=(const float2*)&As[cur][kk][tr*TM];
            float2 a0=ar[0], a1=ar[1], a2=ar[2];
            av[0]=pack2(a0.x,a0.x); av[1]=pack2(a0.y,a0.y);
            av[2]=pack2(a1.x,a1.x); av[3]=pack2(a1.y,a1.y);
            av[4]=pack2(a2.x,a2.x); av[5]=pack2(a2.y,a2.y);
            #pragma unroll
            for(int j=0;j<TN/2;j++) bv[j]=*reinterpret_cast<const ull*>(&Bs2[cur][kk][tc][2*j]);
            #pragma unroll
            for(int i=0;i<TM;i++)
                #pragma unroll
                for(int j=0;j<TN/2;j++) fma2(acc[i][j],av[i],bv[j]);
        }
        if(t+1<ntile){
            int nb=cur^1;
            #pragma unroll
            for(int u=0;u<3;u++){int i=tid+u*NT; As[nb][i%BK][i/BK]=ra[u];}
            #pragma unroll
            for(int u=0;u<4;u++){int i=tid+u*NT; int nn=i/BK; Bs2[nb][i%BK][nn>>3][nn&7]=rb[u];}
            __syncthreads();
        }
    }

    // silu + per-thread row-group partial sum (each thread's 6 rows are in one node)
    const int col0 = n0 + tc*TN;
    float colsum[8] = {0,0,0,0,0,0,0,0};
    #pragma unroll
    for(int i=0;i<TM;i++){
        #pragma unroll
        for(int j=0;j<TN/2;j++){
            float v0,v1; unpack2(acc[i][j],v0,v1);
            colsum[2*j]   += siluf(v0 + bias[col0+2*j]);
            colsum[2*j+1] += siluf(v1 + bias[col0+2*j+1]);
        }
    }
    __syncthreads();
    #pragma unroll
    for(int jj=0;jj<8;jj++) red[tr][tc*TN+jj]=colsum[jj];
    __syncthreads();
    if((tr&3)==0){
        int node = m0/Asz + (tr>>2);
        #pragma unroll
        for(int jj=0;jj<8;jj++){
            int c = tc*TN+jj;
            float s = red[tr][c]+red[tr+1][c]+red[tr+2][c]+red[tr+3][c];
            agg[(size_t)node*Hh + n0 + c] = s*(1.0f/24.0f);
        }
    }
}

// ===== fused: y = nf@w_proj^T + b; nf += silu((LN(y)*fg+fb)*scale + shift) =====
// B smem: [BK][32][10] pad; A read as 1x LDS.128 (broadcast within warp).
__global__ __launch_bounds__(256) void projfilm(
    const float* __restrict__ wproj, const float* __restrict__ bproj,
    const float* __restrict__ cond,  // [B][512]
    const float* __restrict__ fg, const float* __restrict__ fb,
    float* nf)
{
    const int BM=32,BN=256,BK=8,TM=4,TN=8,NT=256,K=Hh;
    __shared__ __align__(16) float As[2][BK][BM];
    __shared__ __align__(16) float Bs2[2][BK][32][10];
    const int tid=threadIdx.x;
    const int tc=tid%32, tr=tid/32;     // warp == fixed tr
    const int m0=blockIdx.x*BM;

    ull acc[TM][TN/2];
    #pragma unroll
    for(int i=0;i<TM;i++)
        #pragma unroll
        for(int j=0;j<TN/2;j++) acc[i][j]=0ULL;

    float ra[1], rb[8];
    { int i=tid; ra[0]=nf[(size_t)(m0+i/BK)*K + i%BK]; }
    #pragma unroll
    for(int u=0;u<8;u++){int i=tid+u*NT; rb[u]=wproj[(size_t)(i/BK)*K + i%BK];}
    { int i=tid; As[0][i%BK][i/BK]=ra[0]; }
    #pragma unroll
    for(int u=0;u<8;u++){int i=tid+u*NT; int nn=i/BK; Bs2[0][i%BK][nn>>3][nn&7]=rb[u];}
    __syncthreads();

    const int ntile=K/BK;
    for(int t=0;t<ntile;t++){
        int cur=t&1;
        if(t+1<ntile){
            int k0=(t+1)*BK;
            { int i=tid; ra[0]=nf[(size_t)(m0+i/BK)*K + k0 + i%BK]; }
            #pragma unroll
            for(int u=0;u<8;u++){int i=tid+u*NT; rb[u]=wproj[(size_t)(i/BK)*K + k0 + i%BK];}
        }
        #pragma unroll
        for(int kk=0;kk<BK;kk++){
            ull av[TM], bv[TN/2];
            float4 a0=*(const float4*)&As[cur][kk][tr*TM];
            av[0]=pack2(a0.x,a0.x); av[1]=pack2(a0.y,a0.y);
            av[2]=pack2(a0.z,a0.z); av[3]=pack2(a0.w,a0.w);
            #pragma unroll
            for(int j=0;j<TN/2;j++) bv[j]=*reinterpret_cast<const ull*>(&Bs2[cur][kk][tc][2*j]);
            #pragma unroll
            for(int i=0;i<TM;i++)
                #pragma unroll
                for(int j=0;j<TN/2;j++) fma2(acc[i][j],av[i],bv[j]);
        }
        if(t+1<ntile){
            int nb=cur^1;
            { int i=tid; As[nb][i%BK][i/BK]=ra[0]; }
            #pragma unroll
            for(int u=0;u<8;u++){int i=tid+u*NT; int nn=i/BK; Bs2[nb][i%BK][nn>>3][nn&7]=rb[u];}
            __syncthreads();
        }
    }

    const int col0 = tc*TN;
    #pragma unroll
    for(int i=0;i<TM;i++){
        int gm = m0 + tr*TM + i;
        int g  = gm/Asz;
        float v[8];
        #pragma unroll
        for(int j=0;j<TN/2;j++) unpack2(acc[i][j], v[2*j], v[2*j+1]);
        #pragma unroll
        for(int jj=0;jj<8;jj++) v[jj] += bproj[col0+jj];
        float s=0.f;
        #pragma unroll
        for(int jj=0;jj<8;jj++) s+=v[jj];
        #pragma unroll
        for(int o=16;o>0;o>>=1) s += __shfl_xor_sync(0xffffffffu, s, o);
        float mu = s*(1.0f/256.0f);
        float ss=0.f;
        #pragma unroll
        for(int jj=0;jj<8;jj++){ v[jj]-=mu; ss+=v[jj]*v[jj]; }
        #pragma unroll
        for(int o=16;o>0;o>>=1) ss += __shfl_xor_sync(0xffffffffu, ss, o);
        float rstd = rsqrtf(ss*(1.0f/256.0f) + 1e-5f);
        #pragma unroll
        for(int jj=0;jj<8;jj++){
            int col = col0+jj;
            float y  = v[jj]*rstd*fg[col] + fb[col];
            float sc = cond[(size_t)g*(2*Hh)+col];
            float sh = cond[(size_t)g*(2*Hh)+Hh+col];
            nf[(size_t)gm*Hh+col] += siluf(y*sc + sh);
        }
    }
}

// ================= old guarded GEMM (cold paths: cond, embed, types) ========
template<int BM,int BN,int BK,int TM,int TN,int AMODE>
__global__ void gemm_k(
    int M, int Nout, int K,
    const float* __restrict__ A, int lda,
    const float* __restrict__ A2, int K1, int lda2,
    const float* __restrict__ W, int ldw,
    const float* __restrict__ bias,
    float* __restrict__ C, int ldc,
    int act)
{
    __shared__ float As[BK][BM];
    __shared__ float Bs[BK][BN];
    const int NT = (BM/TM)*(BN/TN);
    const int tid = threadIdx.x;
    const int tc  = tid % (BN/TN);
    const int tr  = tid / (BN/TN);
    const int m0  = blockIdx.y * BM;
    const int n0  = blockIdx.x * BN;

    float acc[TM][TN];
    #pragma unroll
    for (int i=0;i<TM;i++)
        #pragma unroll
        for (int j=0;j<TN;j++) acc[i][j]=0.f;

    for (int k0 = 0; k0 < K; k0 += BK) {
        for (int i = tid; i < BM*BK; i += NT) {
            int mm = i / BK, kk = i % BK;
            int gm = m0 + mm, gk = k0 + kk;
            float v = 0.f;
            if (gm < M && gk < K) {
                if (AMODE == 0) v = A[(size_t)gm*lda + gk];
                else v = (gk < K1) ? A[(size_t)gm*lda + gk] : A2[(size_t)gm*lda2 + (gk-K1)];
            }
            As[kk][mm] = v;
        }
        for (int i = tid; i < BN*BK; i += NT) {
            int nn = i / BK, kk = i % BK;
            int gn = n0 + nn, gk = k0 + kk;
            Bs[kk][nn] = (gn < Nout && gk < K) ? W[(size_t)gn*ldw + gk] : 0.f;
        }
        __syncthreads();
        #pragma unroll
        for (int kk = 0; kk < BK; kk++) {
            float a[TM], b[TN];
            #pragma unroll
            for (int i=0;i<TM;i++) a[i] = As[kk][tr*TM+i];
            #pragma unroll
            for (int j=0;j<TN;j++) b[j] = Bs[kk][tc*TN+j];
            #pragma unroll
            for (int i=0;i<TM;i++)
                #pragma unroll
                for (int j=0;j<TN;j++) acc[i][j] += a[i]*b[j];
        }
        __syncthreads();
    }

    #pragma unroll
    for (int i=0;i<TM;i++) {
        int gm = m0 + tr*TM + i;
        if (gm >= M) continue;
        #pragma unroll
        for (int j=0;j<TN;j++) {
            int gn = n0 + tc*TN + j;
            if (gn >= Nout) continue;
            float v = acc[i][j];
            if (bias) v += bias[gn];
            if (act)  v = siluf(v);
            C[(size_t)gm*ldc + gn] = v;
        }
    }
}

// ---------------- small kernels ----------------
__global__ void copy_f(const float* __restrict__ a, float* __restrict__ b, int n){
    int i=blockIdx.x*blockDim.x+threadIdx.x; if(i<n) b[i]=a[i];
}
__global__ void latips_kernel(const float* __restrict__ L, float* __restrict__ out){
    int idx = blockIdx.x*blockDim.x+threadIdx.x;
    if (idx >= Bsz*9) return;
    int b = idx/9, r = idx%9, i = r/3, k = r%3;
    out[idx] = L[b*9+i*3+0]*L[b*9+k*3+0] + L[b*9+i*3+1]*L[b*9+k*3+1] + L[b*9+i*3+2]*L[b*9+k*3+2];
}
__global__ void latdemb_kernel(const float* __restrict__ fc, const float* __restrict__ latips,
                               float* __restrict__ out){
    int e = blockIdx.x*blockDim.x+threadIdx.x;
    if (e >= Ee) return;
    int b = e/(Asz*Asz), w = e%(Asz*Asz);
    int a = b*Asz + w/Asz, c = b*Asz + w%Asz;
    float* o = out + (size_t)e*LD_PAD;
    #pragma unroll
    for (int i=0;i<9;i++) o[i] = latips[b*9+i];
    #pragma unroll
    for (int d=0;d<3;d++){
        float df = fc[c*3+d] - fc[a*3+d];
        df -= floorf(df);
        #pragma unroll
        for (int f=0;f<NFREQ;f++){
            float ang = 6.283185307179586f * (float)f * df;
            float sn, cs; sincosf(ang, &sn, &cs);
            o[9 + d*NFREQ + f]      = sn;
            o[9 + 30 + d*NFREQ + f] = cs;
        }
    }
    o[69]=0.f; o[70]=0.f; o[71]=0.f;
}
__global__ void pack_w1r(const float* __restrict__ ew1, float* __restrict__ w1r){
    int i = blockIdx.x*blockDim.x+threadIdx.x;
    if (i >= Hh*LD_PAD) return;
    int n = i/LD_PAD, k = i%LD_PAD;
    w1r[i] = (k < 69) ? ew1[(size_t)n*EDGE_IN + 2*Hh + k] : 0.f;
}
__global__ void gfeat2(const float* __restrict__ nf, float* __restrict__ gf){
    int i=blockIdx.x*blockDim.x+threadIdx.x;
    if (i >= Bsz*Hh) return;
    int b=i/Hh, h=i%Hh;
    float s=0.f;
    #pragma unroll
    for(int a=0;a<Asz;a++) s += nf[(size_t)(b*Asz+a)*Hh+h];
    gf[i]=s;
}
__global__ void lattmp_kernel(const float* __restrict__ gf, const float* __restrict__ w_latt,
                              float* __restrict__ lt){
    int idx = blockIdx.x*blockDim.x+threadIdx.x;
    if (idx >= Bsz*9) return;
    int b = idx/9, r = idx%9;
    float s = 0.f;
    for (int k=0;k<Hh;k++) s += gf[b*Hh+k]*w_latt[r*Hh+k];
    lt[idx] = s * (1.f/(float)Asz);
}
__global__ void lattout_kernel(const float* __restrict__ lt, const float* __restrict__ L,
                               float* __restrict__ out){
    int idx = blockIdx.x*blockDim.x+threadIdx.x;
    if (idx >= Bsz*9) return;
    int b = idx/9, r = idx%9, i = r/3, k = r%3;
    float s = 0.f;
    #pragma unroll
    for (int j=0;j<3;j++) s += lt[b*9+i*3+j]*L[b*9+j*3+k];
    out[idx] = s;
}
__global__ void coords_kernel(const float* __restrict__ nf, const float* __restrict__ wc,
                              float* __restrict__ out){
    int idx = blockIdx.x*blockDim.x+threadIdx.x;
    if (idx >= Nn*3) return;
    int n = idx/3, d = idx%3;
    float s = 0.f;
    for (int k=0;k<Hh;k++) s += nf[(size_t)n*Hh+k]*wc[d*Hh+k];
    out[idx] = s;
}

// ---------------- host-side launch helpers ----------------
static void gemm_guard(int M,int Nout,int K, const float* A,int lda,
                       const float* W,int ldw, const float* bias,
                       float* C,int ldc,int act){
    dim3 grid((Nout+63)/64, (M+63)/64);
    gemm_k<64,64,16,4,4,0><<<grid,256>>>(M,Nout,K, A,lda, nullptr,0,0,
        W,ldw,bias, C,ldc, act);
}
static void gemm_guard_cat(int M,int Nout,int K1,int K2, const float* A1,const float* A2,
                           const float* W,int ldw,const float* bias,
                           float* C,int ldc,int act){
    dim3 grid((Nout+63)/64, (M+63)/64);
    gemm_k<64,64,16,4,4,1><<<grid,256>>>(M,Nout,K1+K2, A1,K1, A2,K1,K2,
        W,ldw,bias, C,ldc, act);
}

extern "C" void kernel_launch(void* const* d_in, const int* in_sizes, int n_in,
                              void* d_out, int out_size){
    const float* atom_types=(const float*)d_in[0];
    const float* frac      =(const float*)d_in[1];
    const float* lattices  =(const float*)d_in[2];
    const float* t         =(const float*)d_in[3];
    const float* text      =(const float*)d_in[4];
    const float* w_emb     =(const float*)d_in[5];
    const float* b_emb     =(const float*)d_in[6];
    const float* w_cond    =(const float*)d_in[7];
    const float* b_cond    =(const float*)d_in[8];
    const float* w_proj    =(const float*)d_in[9];
    const float* b_proj    =(const float*)d_in[10];
    const float* film_g    =(const float*)d_in[11];
    const float* film_b    =(const float*)d_in[12];
    const float* edge_w1   =(const float*)d_in[13];
    const float* edge_b1   =(const float*)d_in[14];
    const float* edge_w2   =(const float*)d_in[15];
    const float* edge_b2   =(const float*)d_in[16];
    const float* node_w1   =(const float*)d_in[17];
    const float* node_b1   =(const float*)d_in[18];
    const float* node_w2   =(const float*)d_in[19];
    const float* node_b2   =(const float*)d_in[20];
    const float* w_coord   =(const float*)d_in[21];
    const float* w_latt    =(const float*)d_in[22];
    const float* w_type    =(const float*)d_in[23];
    const float* b_type    =(const float*)d_in[24];
    float* out = (float*)d_out;

    float *nf,*PQ,*no1,*agg,*ef1,*ldb,*w1r,*cond,*lips,*gf,*ltmp;
    { void* p;
      cudaGetSymbolAddress(&p, g_nf);      nf   = (float*)p;
      cudaGetSymbolAddress(&p, g_PQ);      PQ   = (float*)p;
      cudaGetSymbolAddress(&p, g_no1);     no1  = (float*)p;
      cudaGetSymbolAddress(&p, g_agg);     agg  = (float*)p;
      cudaGetSymbolAddress(&p, g_ef1);     ef1  = (float*)p;
      cudaGetSymbolAddress(&p, g_latdemb); ldb  = (float*)p;
      cudaGetSymbolAddress(&p, g_w1r);     w1r  = (float*)p;
      cudaGetSymbolAddress(&p, g_cond);    cond = (float*)p;
      cudaGetSymbolAddress(&p, g_latips);  lips = (float*)p;
      cudaGetSymbolAddress(&p, g_gfeat);   gf   = (float*)p;
      cudaGetSymbolAddress(&p, g_lattmp);  ltmp = (float*)p;
    }

    // ----- setup -----
    latips_kernel<<<(Bsz*9+255)/256,256>>>(lattices, lips);
    latdemb_kernel<<<(Ee+255)/256,256>>>(frac, lips, ldb);
    gemm_guard_cat(Bsz, 2*Hh, TIMED, TEXTD, t, text, w_cond, TIMED+TEXTD, b_cond, cond, 2*Hh, 1);
    gemm_guard(Nn, Hh, MAXA, atom_types, MAXA, w_emb, MAXA, b_emb, nf, Hh, 0);

    // ----- layers -----
    for (int i=0;i<NLAYERS;i++){
        const float* ew1 = edge_w1 + (size_t)i*Hh*EDGE_IN;
        const float* eb1 = edge_b1 + i*Hh;
        const float* ew2 = edge_w2 + (size_t)i*Hh*Hh;
        const float* eb2 = edge_b2 + i*Hh;
        const float* nw1 = node_w1 + (size_t)i*Hh*2*Hh;
        const float* nb1 = node_b1 + i*Hh;
        const float* nw2 = node_w2 + (size_t)i*Hh*Hh;
        const float* nb2 = node_b2 + i*Hh;

        // fused proj + LN + FiLM + residual into nf
        projfilm<<<Nn/32,256>>>(w_proj, b_proj, cond, film_g, film_b, nf);

        // pack W1's [lat|demb] slice to padded K=72
        pack_w1r<<<(Hh*LD_PAD+255)/256,256>>>(ew1, w1r);

        // PQ = nf @ [W1a ; W1b]^T  (fused P,Q; Nout=512)
        node_gemm<false,true,false,false><<<dim3(8,48),256>>>(
            nf, nullptr, 0.f, ew1, EDGE_IN, nullptr, nullptr, PQ, 2*Hh, Hh);

        // ef1 = silu(latdemb @ W1r^T + P[e0] + Q[e1] + b1)
        edge1_gemm<<<dim3(2,576),256>>>(ldb, w1r, eb1, PQ, ef1);

        // agg[n] = mean over node's 24 edges of silu(ef1 @ W2^T + b2)
        edge2_gemm<<<dim3(2,768),256>>>(ef1, ew2, eb2, agg);

        // no1 = silu([nf, agg] @ nw1^T + nb1)   (agg already divided by deg)
        node_gemm<true,false,true,false><<<dim3(4,48),256>>>(
            nf, agg, 1.0f, nw1, 2*Hh, nb1, nullptr, no1, Hh, 2*Hh);

        // nf += silu(no1 @ nw2^T + nb2)
        node_gemm<false,false,true,true><<<dim3(4,48),256>>>(
            no1, nullptr, 0.f, nw2, Hh, nb2, nf, nf, Hh, Hh);
    }

    // ----- outputs -----
    gemm_guard(Nn, MAXA, Hh, nf, Hh, w_type, Hh, b_type, out + O_TYPES, MAXA, 0);
    gfeat2<<<(Bsz*Hh+255)/256,256>>>(nf, gf);
    lattmp_kernel<<<(Bsz*9+255)/256,256>>>(gf, w_latt, ltmp);
    lattout_kernel<<<(Bsz*9+255)/256,256>>>(ltmp, lattices, out + O_LATT);
    coords_kernel<<<(Nn*3+255)/256,256>>>(nf, w_coord, out + O_COORD);
    copy_f<<<(Nn*Hh+255)/256,256>>>(nf, out + O_NF, Nn*Hh);
}